// round 9
// baseline (speedup 1.0000x reference)
#include <cuda_runtime.h>
#include <cuda_bf16.h>
#include <cstdint>

// ---------------------------------------------------------------------------
// Static device scratch
// ---------------------------------------------------------------------------
#define MMAX 4096
#define KMAX 4096
__device__ unsigned char d_bm[256 * 256];
__device__ __nv_bfloat16 d_A2[(size_t)MMAX * 2 * KMAX];   // 64 MB: A hi/lo packed
__device__ __nv_bfloat16 d_W2[(size_t)MMAX * 2 * KMAX];   // 64 MB: W hi/lo packed

// ---------------------------------------------------------------------------
// PTX helpers (sm_80-level features only: cp.async, ldmatrix, mma.sync)
// ---------------------------------------------------------------------------
__device__ __forceinline__ uint32_t smem_addr(const void* p) {
    uint32_t a;
    asm("{ .reg .u64 t; cvta.to.shared.u64 t, %1; cvt.u32.u64 %0, t; }" : "=r"(a) : "l"(p));
    return a;
}
__device__ __forceinline__ void cp16(uint32_t dst, const void* src, int srcsz) {
    asm volatile("cp.async.cg.shared.global [%0], [%1], 16, %2;"
                 :: "r"(dst), "l"(src), "r"(srcsz) : "memory");
}
__device__ __forceinline__ void cp_commit() { asm volatile("cp.async.commit_group;" ::: "memory"); }
template <int N> __device__ __forceinline__ void cp_wait() {
    asm volatile("cp.async.wait_group %0;" :: "n"(N) : "memory");
}
__device__ __forceinline__ void ldmx4(uint32_t* r, uint32_t a) {
    asm volatile("ldmatrix.sync.aligned.m8n8.x4.shared.b16 {%0,%1,%2,%3}, [%4];"
                 : "=r"(r[0]), "=r"(r[1]), "=r"(r[2]), "=r"(r[3]) : "r"(a));
}
__device__ __forceinline__ void mma16816(float* c, const uint32_t* a, const uint32_t* b) {
    asm volatile(
        "mma.sync.aligned.m16n8k16.row.col.f32.bf16.bf16.f32 "
        "{%0,%1,%2,%3}, {%4,%5,%6,%7}, {%8,%9}, {%0,%1,%2,%3};"
        : "+f"(c[0]), "+f"(c[1]), "+f"(c[2]), "+f"(c[3])
        : "r"(a[0]), "r"(a[1]), "r"(a[2]), "r"(a[3]), "r"(b[0]), "r"(b[1]));
}

#define SWZ(o) ((o) ^ (((o) >> 3) & 0x70))

// Dynamic smem layout: 2-stage pipeline (proven R6 config), 32KB/stage
#define SM_A(b)   ((b) * 32768)
#define SM_W(b)   ((b) * 32768 + 16384)
#define SM_FLAGS  65536   // 4*256 bytes
#define SM_LIST   66560   // 256 * u16
#define SM_BIAS   67072   // 128 * f32
#define SM_MISC   67584   // [0]=count
#define SMEM_TOTAL 68608

// ---------------------------------------------------------------------------
// Kernel 1: pool element mask [N,K] into 32x32 block activity d_bm[Nb,Kb]
// ---------------------------------------------------------------------------
__global__ void blockmask_kernel(const int* __restrict__ mask, int K, int Kb) {
    int nb = blockIdx.x / Kb;
    int kb = blockIdx.x - nb * Kb;
    int r  = threadIdx.x >> 3;
    int c4 = threadIdx.x & 7;
    const int4* p = (const int4*)(mask + (size_t)(nb * 32 + r) * K + kb * 32 + c4 * 4);
    int4 v = *p;
    int any = __syncthreads_or(v.x | v.y | v.z | v.w);
    if (threadIdx.x == 0) d_bm[nb * Kb + kb] = any ? 1 : 0;
}

// ---------------------------------------------------------------------------
// Kernel 2: pack fp32 -> bf16 hi/lo, chunk-interleaved per 32-K-chunk:
//   out[m][c*64 + j]      = bf16(x)     (j = k&31, c = k>>5)
//   out[m][c*64 + 32 + j] = bf16(x - hi)
// Each packed row chunk = 128 bytes = one SW128 swizzle atom row.
// ---------------------------------------------------------------------------
__device__ __forceinline__ void pack_row(const float* __restrict__ src,
                                         __nv_bfloat16* __restrict__ dst, int K) {
    const int m = blockIdx.x;
    const float* row = src + (size_t)m * K;
    __nv_bfloat16* out = dst + (size_t)m * 2 * K;
    for (int p = threadIdx.x; p < (K >> 1); p += blockDim.x) {
        int k = p << 1;
        float2 v = *(const float2*)(row + k);
        __nv_bfloat16 h0 = __float2bfloat16(v.x);
        __nv_bfloat16 h1 = __float2bfloat16(v.y);
        __nv_bfloat162 hv; hv.x = h0; hv.y = h1;
        __nv_bfloat162 lv;
        lv.x = __float2bfloat16(v.x - __bfloat162float(h0));
        lv.y = __float2bfloat16(v.y - __bfloat162float(h1));
        int c = k >> 5, j = k & 31;
        *(__nv_bfloat162*)(out + (size_t)c * 64 + j)      = hv;
        *(__nv_bfloat162*)(out + (size_t)c * 64 + 32 + j) = lv;
    }
}
__global__ void pack_a_kernel(const float* __restrict__ src, int K) { pack_row(src, d_A2, K); }
__global__ void pack_w_kernel(const float* __restrict__ src, int K) { pack_row(src, d_W2, K); }

// ---------------------------------------------------------------------------
// Kernel 3: block-sparse bf16x3 GEMM via mma.sync (HMMA.16816.F32.BF16).
// C[M,N] = A*W^T + bias. CTA: 128x128, 8 warps as 4(m) x 2(n), warp = 32m x 64n.
// R6's proven 2-stage cp.async double-buffer (two barriers per chunk), plus
// fragment double-buffering: step j+1's 6 ldmatrix issued before step j's
// 16 MMAs, hiding LDSM latency under the tensor stream.
// ---------------------------------------------------------------------------
__global__ __launch_bounds__(256)
void mma_gemm(const float* __restrict__ bias, float* __restrict__ C,
              int M, int N, int K, int Kb)
{
    extern __shared__ __align__(1024) char sm[];
    const int tid  = threadIdx.x;
    const int lane = tid & 31;
    const int wid  = tid >> 5;
    const int n0 = blockIdx.x * 128;
    const int m0 = blockIdx.y * 128;
    const int nb0 = n0 >> 5;
    const size_t twoK = (size_t)2 * K;

    unsigned char*  s_flags = (unsigned char*)(sm + SM_FLAGS);
    unsigned short* s_list  = (unsigned short*)(sm + SM_LIST);
    float*          s_bias  = (float*)(sm + SM_BIAS);
    volatile int*   s_misc  = (volatile int*)(sm + SM_MISC);
    const uint32_t smb = smem_addr(sm);

    for (int i = tid; i < 4 * Kb; i += 256) {
        int r = i / Kb, c = i - r * Kb;
        s_flags[r * 256 + c] = d_bm[(size_t)(nb0 + r) * Kb + c];
    }
    if (tid < 128) s_bias[tid] = bias[n0 + tid];
    __syncthreads();
    if (tid == 0) {
        int cnt = 0;
        for (int kb = 0; kb < Kb; kb++)
            if (s_flags[kb] | s_flags[256 + kb] | s_flags[512 + kb] | s_flags[768 + kb])
                s_list[cnt++] = (unsigned short)kb;
        s_misc[0] = cnt;
    }
    __syncthreads();
    const int cnt = s_misc[0];

    // Warp tiling: 4(m) x 2(n), warp = 32m x 64n
    const int wm32 = (wid & 3) * 32;
    const int wn64 = (wid >> 2) * 64;

    // ldmatrix per-lane addressing components
    const int a_row = ((lane >> 3) & 1) * 8 + (lane & 7);
    const int a_ks  = (lane >> 4) & 1;
    const int b_r   = lane & 7;
    const int b_ks  = (lane >> 3) & 1;
    const int b_ts  = (lane >> 4) & 1;

    // cp.async coords
    const int lrow = tid >> 3;        // 0..31 (+32*i)
    const int lc16 = tid & 7;         // 16B segment within 128B row

    float acc[2][8][4];
#pragma unroll
    for (int mt = 0; mt < 2; mt++)
#pragma unroll
        for (int nt = 0; nt < 8; nt++)
#pragma unroll
            for (int q = 0; q < 4; q++) acc[mt][nt][q] = 0.f;

#define LOAD_CHUNK(KB, BUF)                                                        \
    do {                                                                           \
        const int kb_ = (KB);                                                      \
        const uint32_t ab_ = smb + SM_A(BUF);                                      \
        const uint32_t wb_ = smb + SM_W(BUF);                                      \
        const __nv_bfloat16* ga_ = d_A2 + (size_t)m0 * twoK + (size_t)kb_ * 64;    \
        const __nv_bfloat16* gw_ = d_W2 + (size_t)n0 * twoK + (size_t)kb_ * 64;    \
        _Pragma("unroll")                                                          \
        for (int it_ = 0; it_ < 4; it_++) {                                        \
            const int row_ = lrow + it_ * 32;                                      \
            const uint32_t so_ = SWZ(row_ * 128 + lc16 * 16);                      \
            cp16(ab_ + so_, ga_ + (size_t)row_ * twoK + lc16 * 8, 16);             \
            const int sz_ = s_flags[((row_ >> 5) << 8) + kb_] ? 16 : 0;            \
            cp16(wb_ + so_, gw_ + (size_t)row_ * twoK + lc16 * 8, sz_);            \
        }                                                                          \
        cp_commit();                                                               \
    } while (0)

    if (cnt > 0) {
        LOAD_CHUNK((int)s_list[0], 0);

        uint32_t afr[2][2][4];   // [stage][mt][frag]
        uint32_t bfr[2][4][4];   // [stage][nq][frag]

        for (int i = 0; i < cnt; i++) {
            const int cur = i & 1;
            if (i + 1 < cnt) {
                LOAD_CHUNK((int)s_list[i + 1], cur ^ 1);
                cp_wait<1>();          // chunk i landed; i+1 may remain in flight
            } else {
                cp_wait<0>();
            }
            __syncthreads();           // tile visible to all warps

            const uint32_t ab = smb + SM_A(cur);
            const uint32_t wb = smb + SM_W(cur);

            // 6 steps: (p,s) = (0,0),(0,1),(1,0),(1,1),(2,0),(2,1)
            // A operand half: hi,hi,lo -> Ab=(p==2)*64 ; W half: hi,lo,hi -> Bb=(p==1)*64
#define LD_FRAGS(J, ST)                                                            \
            do {                                                                   \
                const int p_ = (J) >> 1, s_ = (J) & 1;                             \
                const int Ab_ = (p_ == 2) ? 64 : 0;                                \
                const int Bb_ = (p_ == 1) ? 64 : 0;                                \
                _Pragma("unroll")                                                  \
                for (int mt = 0; mt < 2; mt++)                                     \
                    ldmx4(afr[ST][mt], ab + SWZ((wm32 + mt * 16 + a_row) * 128 +   \
                                                Ab_ + s_ * 32 + a_ks * 16));       \
                _Pragma("unroll")                                                  \
                for (int j4 = 0; j4 < 4; j4++)                                     \
                    ldmx4(bfr[ST][j4], wb + SWZ((wn64 + (2 * j4 + b_ts) * 8 + b_r) \
                                                * 128 + Bb_ + s_ * 32 + b_ks * 16));\
            } while (0)

            LD_FRAGS(0, 0);
#pragma unroll
            for (int j = 0; j < 6; j++) {
                if (j < 5) LD_FRAGS(j + 1, (j + 1) & 1);   // prefetch next step
                const int st = j & 1;
#pragma unroll
                for (int mt = 0; mt < 2; mt++)
#pragma unroll
                    for (int nt = 0; nt < 8; nt++)
                        mma16816(acc[mt][nt], afr[st][mt], &bfr[st][nt >> 1][(nt & 1) * 2]);
            }
#undef LD_FRAGS
            __syncthreads();           // all warps done with buffer cur (R6-proven)
        }
    }

    // Epilogue: acc + bias -> C (covers cnt==0: acc stays zero)
#pragma unroll
    for (int mt = 0; mt < 2; mt++) {
        const int gm = m0 + wm32 + mt * 16 + (lane >> 2);
#pragma unroll
        for (int nt = 0; nt < 8; nt++) {
            const int bn = wn64 + nt * 8 + (lane & 3) * 2;
            const float b0 = s_bias[bn], b1 = s_bias[bn + 1];
            float2 o0 = make_float2(acc[mt][nt][0] + b0, acc[mt][nt][1] + b1);
            float2 o1 = make_float2(acc[mt][nt][2] + b0, acc[mt][nt][3] + b1);
            *(float2*)(C + (size_t)gm * N + n0 + bn)       = o0;
            *(float2*)(C + (size_t)(gm + 8) * N + n0 + bn) = o1;
        }
    }
#undef LOAD_CHUNK
}

// ---------------------------------------------------------------------------
// Launch: inputs [data(B,S,K) f32, mask(N,K) i32, weight(N,K) f32, bias(N) f32]
// ---------------------------------------------------------------------------
extern "C" void kernel_launch(void* const* d_in, const int* in_sizes, int n_in,
                              void* d_out, int out_size) {
    const float* data   = (const float*)d_in[0];
    const int*   mask   = (const int*)d_in[1];
    const float* weight = (const float*)d_in[2];
    const float* bias   = (const float*)d_in[3];
    float* out = (float*)d_out;

    const int N = in_sizes[3];
    const int K = in_sizes[1] / N;
    const int M = in_sizes[0] / K;
    const int Kb = K / 32;
    const int Nb = N / 32;

    cudaFuncSetAttribute(mma_gemm, cudaFuncAttributeMaxDynamicSharedMemorySize, SMEM_TOTAL);

    blockmask_kernel<<<Nb * Kb, 256>>>(mask, K, Kb);
    pack_a_kernel<<<M, 256>>>(data, K);
    pack_w_kernel<<<N, 256>>>(weight, K);

    dim3 grid(N / 128, M / 128);
    mma_gemm<<<grid, 256, SMEM_TOTAL>>>(bias, out, M, N, K, Kb);
}

// round 10
// speedup vs baseline: 1.0480x; 1.0480x over previous
#include <cuda_runtime.h>
#include <cuda_bf16.h>
#include <cstdint>

// ---------------------------------------------------------------------------
// Static device scratch
// ---------------------------------------------------------------------------
#define MMAX 4096
#define KMAX 4096
__device__ unsigned char d_bm[256 * 256];
__device__ __nv_bfloat16 d_A2[(size_t)MMAX * 2 * KMAX];   // 64 MB: A hi/lo packed
__device__ __nv_bfloat16 d_W2[(size_t)MMAX * 2 * KMAX];   // 64 MB: W hi/lo packed

// ---------------------------------------------------------------------------
// PTX helpers (sm_80-level features only: cp.async, ldmatrix, mma.sync)
// ---------------------------------------------------------------------------
__device__ __forceinline__ uint32_t smem_addr(const void* p) {
    uint32_t a;
    asm("{ .reg .u64 t; cvta.to.shared.u64 t, %1; cvt.u32.u64 %0, t; }" : "=r"(a) : "l"(p));
    return a;
}
__device__ __forceinline__ void cp16(uint32_t dst, const void* src, int srcsz) {
    asm volatile("cp.async.cg.shared.global [%0], [%1], 16, %2;"
                 :: "r"(dst), "l"(src), "r"(srcsz) : "memory");
}
__device__ __forceinline__ void cp_commit() { asm volatile("cp.async.commit_group;" ::: "memory"); }
template <int N> __device__ __forceinline__ void cp_wait() {
    asm volatile("cp.async.wait_group %0;" :: "n"(N) : "memory");
}
__device__ __forceinline__ void ldmx4(uint32_t* r, uint32_t a) {
    asm volatile("ldmatrix.sync.aligned.m8n8.x4.shared.b16 {%0,%1,%2,%3}, [%4];"
                 : "=r"(r[0]), "=r"(r[1]), "=r"(r[2]), "=r"(r[3]) : "r"(a));
}
__device__ __forceinline__ void mma16816(float* c, const uint32_t* a, const uint32_t* b) {
    asm volatile(
        "mma.sync.aligned.m16n8k16.row.col.f32.bf16.bf16.f32 "
        "{%0,%1,%2,%3}, {%4,%5,%6,%7}, {%8,%9}, {%0,%1,%2,%3};"
        : "+f"(c[0]), "+f"(c[1]), "+f"(c[2]), "+f"(c[3])
        : "r"(a[0]), "r"(a[1]), "r"(a[2]), "r"(a[3]), "r"(b[0]), "r"(b[1]));
}

#define SWZ(o) ((o) ^ (((o) >> 3) & 0x70))

// Dynamic smem layout: 3-stage pipeline, 32KB/stage (A 16KB | W 16KB)
#define SM_A(b)   ((b) * 32768)
#define SM_W(b)   ((b) * 32768 + 16384)
#define SM_FLAGS  98304    // 4*256 bytes
#define SM_LIST   99328    // 256 * u16
#define SM_BIAS   99840    // 128 * f32
#define SM_MISC   100352   // [0]=count
#define SMEM_TOTAL 101376

// ---------------------------------------------------------------------------
// Kernel 1: pool element mask [N,K] into 32x32 block activity d_bm[Nb,Kb]
// ---------------------------------------------------------------------------
__global__ void blockmask_kernel(const int* __restrict__ mask, int K, int Kb) {
    int nb = blockIdx.x / Kb;
    int kb = blockIdx.x - nb * Kb;
    int r  = threadIdx.x >> 3;
    int c4 = threadIdx.x & 7;
    const int4* p = (const int4*)(mask + (size_t)(nb * 32 + r) * K + kb * 32 + c4 * 4);
    int4 v = *p;
    int any = __syncthreads_or(v.x | v.y | v.z | v.w);
    if (threadIdx.x == 0) d_bm[nb * Kb + kb] = any ? 1 : 0;
}

// ---------------------------------------------------------------------------
// Kernel 2: pack fp32 -> bf16 hi/lo, chunk-interleaved per 32-K-chunk:
//   out[m][c*64 + j]      = bf16(x)     (j = k&31, c = k>>5)
//   out[m][c*64 + 32 + j] = bf16(x - hi)
// Each packed row chunk = 128 bytes = one SW128 swizzle atom row.
// ---------------------------------------------------------------------------
__device__ __forceinline__ void pack_row(const float* __restrict__ src,
                                         __nv_bfloat16* __restrict__ dst, int K) {
    const int m = blockIdx.x;
    const float* row = src + (size_t)m * K;
    __nv_bfloat16* out = dst + (size_t)m * 2 * K;
    for (int p = threadIdx.x; p < (K >> 1); p += blockDim.x) {
        int k = p << 1;
        float2 v = *(const float2*)(row + k);
        __nv_bfloat16 h0 = __float2bfloat16(v.x);
        __nv_bfloat16 h1 = __float2bfloat16(v.y);
        __nv_bfloat162 hv; hv.x = h0; hv.y = h1;
        __nv_bfloat162 lv;
        lv.x = __float2bfloat16(v.x - __bfloat162float(h0));
        lv.y = __float2bfloat16(v.y - __bfloat162float(h1));
        int c = k >> 5, j = k & 31;
        *(__nv_bfloat162*)(out + (size_t)c * 64 + j)      = hv;
        *(__nv_bfloat162*)(out + (size_t)c * 64 + 32 + j) = lv;
    }
}
__global__ void pack_a_kernel(const float* __restrict__ src, int K) { pack_row(src, d_A2, K); }
__global__ void pack_w_kernel(const float* __restrict__ src, int K) { pack_row(src, d_W2, K); }

// ---------------------------------------------------------------------------
// Kernel 3: block-sparse bf16x3 GEMM via mma.sync (HMMA.16816.F32.BF16).
// C[M,N] = A*W^T + bias. CTA: 128x128, 8 warps as 4(m) x 2(n), warp = 32m x 64n.
// 3-stage cp.async pipeline, ONE barrier per chunk, load issued AFTER the
// barrier: iter i = wait(chunk i) -> barrier -> issue load(i+2) -> compute(i).
// Buf (i+2)%3 == (i-1)%3 and barrier i proves compute i-1 is done everywhere,
// so 3 stages suffice. Per k16-segment s, Ahi/Alo/Whi/Wlo are each loaded
// ONCE (12 ldmx4) and feed all 3 passes (48 MMAs) -- 24 ldmx4/chunk vs 36.
// ---------------------------------------------------------------------------
__global__ __launch_bounds__(256)
void mma_gemm(const float* __restrict__ bias, float* __restrict__ C,
              int M, int N, int K, int Kb)
{
    extern __shared__ __align__(1024) char sm[];
    const int tid  = threadIdx.x;
    const int lane = tid & 31;
    const int wid  = tid >> 5;
    const int n0 = blockIdx.x * 128;
    const int m0 = blockIdx.y * 128;
    const int nb0 = n0 >> 5;
    const size_t twoK = (size_t)2 * K;

    unsigned char*  s_flags = (unsigned char*)(sm + SM_FLAGS);
    unsigned short* s_list  = (unsigned short*)(sm + SM_LIST);
    float*          s_bias  = (float*)(sm + SM_BIAS);
    volatile int*   s_misc  = (volatile int*)(sm + SM_MISC);
    const uint32_t smb = smem_addr(sm);

    for (int i = tid; i < 4 * Kb; i += 256) {
        int r = i / Kb, c = i - r * Kb;
        s_flags[r * 256 + c] = d_bm[(size_t)(nb0 + r) * Kb + c];
    }
    if (tid < 128) s_bias[tid] = bias[n0 + tid];
    __syncthreads();
    if (tid == 0) {
        int cnt = 0;
        for (int kb = 0; kb < Kb; kb++)
            if (s_flags[kb] | s_flags[256 + kb] | s_flags[512 + kb] | s_flags[768 + kb])
                s_list[cnt++] = (unsigned short)kb;
        s_misc[0] = cnt;
    }
    __syncthreads();
    const int cnt = s_misc[0];

    // Warp tiling: 4(m) x 2(n), warp = 32m x 64n
    const int wm32 = (wid & 3) * 32;
    const int wn64 = (wid >> 2) * 64;

    // ldmatrix per-lane addressing components
    const int a_row = ((lane >> 3) & 1) * 8 + (lane & 7);
    const int a_ks  = (lane >> 4) & 1;
    const int b_r   = lane & 7;
    const int b_ks  = (lane >> 3) & 1;
    const int b_ts  = (lane >> 4) & 1;

    // cp.async coords
    const int lrow = tid >> 3;        // 0..31 (+32*i)
    const int lc16 = tid & 7;         // 16B segment within 128B row

    float acc[2][8][4];
#pragma unroll
    for (int mt = 0; mt < 2; mt++)
#pragma unroll
        for (int nt = 0; nt < 8; nt++)
#pragma unroll
            for (int q = 0; q < 4; q++) acc[mt][nt][q] = 0.f;

#define LOAD_CHUNK(KB, BUF)                                                        \
    do {                                                                           \
        const int kb_ = (KB);                                                      \
        const uint32_t ab_ = smb + SM_A(BUF);                                      \
        const uint32_t wb_ = smb + SM_W(BUF);                                      \
        const __nv_bfloat16* ga_ = d_A2 + (size_t)m0 * twoK + (size_t)kb_ * 64;    \
        const __nv_bfloat16* gw_ = d_W2 + (size_t)n0 * twoK + (size_t)kb_ * 64;    \
        _Pragma("unroll")                                                          \
        for (int it_ = 0; it_ < 4; it_++) {                                        \
            const int row_ = lrow + it_ * 32;                                      \
            const uint32_t so_ = SWZ(row_ * 128 + lc16 * 16);                      \
            cp16(ab_ + so_, ga_ + (size_t)row_ * twoK + lc16 * 8, 16);             \
            const int sz_ = s_flags[((row_ >> 5) << 8) + kb_] ? 16 : 0;            \
            cp16(wb_ + so_, gw_ + (size_t)row_ * twoK + lc16 * 8, sz_);            \
        }                                                                          \
        cp_commit();                                                               \
    } while (0)

    if (cnt > 0) {
        LOAD_CHUNK((int)s_list[0], 0);
        if (cnt > 1) LOAD_CHUNK((int)s_list[1], 1);

        int cur = 0;
        for (int i = 0; i < cnt; i++) {
            if (i + 1 < cnt) cp_wait<1>(); else cp_wait<0>();   // chunk i landed
            __syncthreads();                                    // single barrier/chunk
            if (i + 2 < cnt) {
                int nxt = cur + 2; if (nxt >= 3) nxt -= 3;
                LOAD_CHUNK((int)s_list[i + 2], nxt);            // overlaps with compute
            }

            const uint32_t ab = smb + SM_A(cur);
            const uint32_t wb = smb + SM_W(cur);

#pragma unroll
            for (int s = 0; s < 2; s++) {
                uint32_t ahi[2][4], alo[2][4], whi[4][4], wlo[4][4];
#pragma unroll
                for (int mt = 0; mt < 2; mt++) {
                    const uint32_t abase = (wm32 + mt * 16 + a_row) * 128 + s * 32 + a_ks * 16;
                    ldmx4(ahi[mt], ab + SWZ(abase));
                    ldmx4(alo[mt], ab + SWZ(abase + 64));
                }
#pragma unroll
                for (int j4 = 0; j4 < 4; j4++) {
                    const uint32_t wbase = (wn64 + (2 * j4 + b_ts) * 8 + b_r) * 128 + s * 32 + b_ks * 16;
                    ldmx4(whi[j4], wb + SWZ(wbase));
                    ldmx4(wlo[j4], wb + SWZ(wbase + 64));
                }
                // pass 1: Ahi * Whi
#pragma unroll
                for (int mt = 0; mt < 2; mt++)
#pragma unroll
                    for (int nt = 0; nt < 8; nt++)
                        mma16816(acc[mt][nt], ahi[mt], &whi[nt >> 1][(nt & 1) * 2]);
                // pass 2: Ahi * Wlo
#pragma unroll
                for (int mt = 0; mt < 2; mt++)
#pragma unroll
                    for (int nt = 0; nt < 8; nt++)
                        mma16816(acc[mt][nt], ahi[mt], &wlo[nt >> 1][(nt & 1) * 2]);
                // pass 3: Alo * Whi
#pragma unroll
                for (int mt = 0; mt < 2; mt++)
#pragma unroll
                    for (int nt = 0; nt < 8; nt++)
                        mma16816(acc[mt][nt], alo[mt], &whi[nt >> 1][(nt & 1) * 2]);
            }
            if (++cur >= 3) cur = 0;
        }
    }

    // Epilogue: acc + bias -> C (covers cnt==0: acc stays zero)
#pragma unroll
    for (int mt = 0; mt < 2; mt++) {
        const int gm = m0 + wm32 + mt * 16 + (lane >> 2);
#pragma unroll
        for (int nt = 0; nt < 8; nt++) {
            const int bn = wn64 + nt * 8 + (lane & 3) * 2;
            const float b0 = s_bias[bn], b1 = s_bias[bn + 1];
            float2 o0 = make_float2(acc[mt][nt][0] + b0, acc[mt][nt][1] + b1);
            float2 o1 = make_float2(acc[mt][nt][2] + b0, acc[mt][nt][3] + b1);
            *(float2*)(C + (size_t)gm * N + n0 + bn)       = o0;
            *(float2*)(C + (size_t)(gm + 8) * N + n0 + bn) = o1;
        }
    }
#undef LOAD_CHUNK
}

// ---------------------------------------------------------------------------
// Launch: inputs [data(B,S,K) f32, mask(N,K) i32, weight(N,K) f32, bias(N) f32]
// ---------------------------------------------------------------------------
extern "C" void kernel_launch(void* const* d_in, const int* in_sizes, int n_in,
                              void* d_out, int out_size) {
    const float* data   = (const float*)d_in[0];
    const int*   mask   = (const int*)d_in[1];
    const float* weight = (const float*)d_in[2];
    const float* bias   = (const float*)d_in[3];
    float* out = (float*)d_out;

    const int N = in_sizes[3];
    const int K = in_sizes[1] / N;
    const int M = in_sizes[0] / K;
    const int Kb = K / 32;
    const int Nb = N / 32;

    cudaFuncSetAttribute(mma_gemm, cudaFuncAttributeMaxDynamicSharedMemorySize, SMEM_TOTAL);

    blockmask_kernel<<<Nb * Kb, 256>>>(mask, K, Kb);
    pack_a_kernel<<<M, 256>>>(data, K);
    pack_w_kernel<<<N, 256>>>(weight, K);

    dim3 grid(N / 128, M / 128);
    mma_gemm<<<grid, 256, SMEM_TOTAL>>>(bias, out, M, N, K, Kb);
}

// round 11
// speedup vs baseline: 1.8812x; 1.7950x over previous
#include <cuda_runtime.h>
#include <cuda_bf16.h>
#include <cstdint>

// ---------------------------------------------------------------------------
// Static device scratch
// ---------------------------------------------------------------------------
#define MMAX 4096
#define KMAX 4096
__device__ unsigned char d_bm[256 * 256];
__device__ __nv_bfloat16 d_A2[(size_t)MMAX * 2 * KMAX];   // 64 MB: A hi/lo packed
__device__ __nv_bfloat16 d_W2[(size_t)MMAX * 2 * KMAX];   // 64 MB: W hi/lo packed

// ---------------------------------------------------------------------------
// PTX helpers (sm_80-level features only: cp.async, ldmatrix, mma.sync)
// ---------------------------------------------------------------------------
__device__ __forceinline__ uint32_t smem_addr(const void* p) {
    uint32_t a;
    asm("{ .reg .u64 t; cvta.to.shared.u64 t, %1; cvt.u32.u64 %0, t; }" : "=r"(a) : "l"(p));
    return a;
}
__device__ __forceinline__ void cp16(uint32_t dst, const void* src, int srcsz) {
    asm volatile("cp.async.cg.shared.global [%0], [%1], 16, %2;"
                 :: "r"(dst), "l"(src), "r"(srcsz) : "memory");
}
__device__ __forceinline__ void cp_commit() { asm volatile("cp.async.commit_group;" ::: "memory"); }
template <int N> __device__ __forceinline__ void cp_wait() {
    asm volatile("cp.async.wait_group %0;" :: "n"(N) : "memory");
}
__device__ __forceinline__ void ldmx4(uint32_t* r, uint32_t a) {
    asm volatile("ldmatrix.sync.aligned.m8n8.x4.shared.b16 {%0,%1,%2,%3}, [%4];"
                 : "=r"(r[0]), "=r"(r[1]), "=r"(r[2]), "=r"(r[3]) : "r"(a));
}
__device__ __forceinline__ void mma16816(float* c, const uint32_t* a, const uint32_t* b) {
    asm volatile(
        "mma.sync.aligned.m16n8k16.row.col.f32.bf16.bf16.f32 "
        "{%0,%1,%2,%3}, {%4,%5,%6,%7}, {%8,%9}, {%0,%1,%2,%3};"
        : "+f"(c[0]), "+f"(c[1]), "+f"(c[2]), "+f"(c[3])
        : "r"(a[0]), "r"(a[1]), "r"(a[2]), "r"(a[3]), "r"(b[0]), "r"(b[1]));
}

#define SWZ(o) ((o) ^ (((o) >> 3) & 0x70))

// Dynamic smem layout: 3-stage pipeline, 32KB/stage (A 16KB | W 16KB)
#define SM_A(b)   ((b) * 32768)
#define SM_W(b)   ((b) * 32768 + 16384)
#define SM_FLAGS  98304    // 4*256 bytes
#define SM_LIST   99328    // 256 * u16
#define SM_BIAS   99840    // 128 * f32
#define SM_MISC   100352   // [0]=count
#define SMEM_TOTAL 101376

// ---------------------------------------------------------------------------
// Kernel 1: pool element mask [N,K] into 32x32 block activity d_bm[Nb,Kb]
// ---------------------------------------------------------------------------
__global__ void blockmask_kernel(const int* __restrict__ mask, int K, int Kb) {
    int nb = blockIdx.x / Kb;
    int kb = blockIdx.x - nb * Kb;
    int r  = threadIdx.x >> 3;
    int c4 = threadIdx.x & 7;
    const int4* p = (const int4*)(mask + (size_t)(nb * 32 + r) * K + kb * 32 + c4 * 4);
    int4 v = *p;
    int any = __syncthreads_or(v.x | v.y | v.z | v.w);
    if (threadIdx.x == 0) d_bm[nb * Kb + kb] = any ? 1 : 0;
}

// ---------------------------------------------------------------------------
// Kernel 2: pack fp32 -> bf16 hi/lo, chunk-interleaved per 32-K-chunk:
//   out[m][c*64 + j]      = bf16(x)     (j = k&31, c = k>>5)
//   out[m][c*64 + 32 + j] = bf16(x - hi)
// Each packed row chunk = 128 bytes = one SW128 swizzle atom row.
// ---------------------------------------------------------------------------
__device__ __forceinline__ void pack_row(const float* __restrict__ src,
                                         __nv_bfloat16* __restrict__ dst, int K) {
    const int m = blockIdx.x;
    const float* row = src + (size_t)m * K;
    __nv_bfloat16* out = dst + (size_t)m * 2 * K;
    for (int p = threadIdx.x; p < (K >> 1); p += blockDim.x) {
        int k = p << 1;
        float2 v = *(const float2*)(row + k);
        __nv_bfloat16 h0 = __float2bfloat16(v.x);
        __nv_bfloat16 h1 = __float2bfloat16(v.y);
        __nv_bfloat162 hv; hv.x = h0; hv.y = h1;
        __nv_bfloat162 lv;
        lv.x = __float2bfloat16(v.x - __bfloat162float(h0));
        lv.y = __float2bfloat16(v.y - __bfloat162float(h1));
        int c = k >> 5, j = k & 31;
        *(__nv_bfloat162*)(out + (size_t)c * 64 + j)      = hv;
        *(__nv_bfloat162*)(out + (size_t)c * 64 + 32 + j) = lv;
    }
}
__global__ void pack_a_kernel(const float* __restrict__ src, int K) { pack_row(src, d_A2, K); }
__global__ void pack_w_kernel(const float* __restrict__ src, int K) { pack_row(src, d_W2, K); }

// ---------------------------------------------------------------------------
// Kernel 3: block-sparse bf16x3 GEMM via mma.sync (HMMA.16816.F32.BF16).
// C[M,N] = A*W^T + bias. CTA: 128x128, 8 warps as 4(m) x 2(n), warp = 32m x 64n.
// 3-stage cp.async pipeline, ONE barrier per chunk (R10-proven skeleton).
// NEW: block-granular MMA skip. Each warp owns two 32-wide N mask blocks;
// per chunk it computes only the active half(s) and skips entirely (LDSM+MMA)
// when both are inactive. Skipped blocks have W == 0, so acc is unchanged --
// bit-identical result, ~2.5x fewer HMMAs.
// ---------------------------------------------------------------------------
__global__ __launch_bounds__(256)
void mma_gemm(const float* __restrict__ bias, float* __restrict__ C,
              int M, int N, int K, int Kb)
{
    extern __shared__ __align__(1024) char sm[];
    const int tid  = threadIdx.x;
    const int lane = tid & 31;
    const int wid  = tid >> 5;
    const int n0 = blockIdx.x * 128;
    const int m0 = blockIdx.y * 128;
    const int nb0 = n0 >> 5;
    const size_t twoK = (size_t)2 * K;

    unsigned char*  s_flags = (unsigned char*)(sm + SM_FLAGS);
    unsigned short* s_list  = (unsigned short*)(sm + SM_LIST);
    float*          s_bias  = (float*)(sm + SM_BIAS);
    volatile int*   s_misc  = (volatile int*)(sm + SM_MISC);
    const uint32_t smb = smem_addr(sm);

    for (int i = tid; i < 4 * Kb; i += 256) {
        int r = i / Kb, c = i - r * Kb;
        s_flags[r * 256 + c] = d_bm[(size_t)(nb0 + r) * Kb + c];
    }
    if (tid < 128) s_bias[tid] = bias[n0 + tid];
    __syncthreads();
    if (tid == 0) {
        int cnt = 0;
        for (int kb = 0; kb < Kb; kb++)
            if (s_flags[kb] | s_flags[256 + kb] | s_flags[512 + kb] | s_flags[768 + kb])
                s_list[cnt++] = (unsigned short)kb;
        s_misc[0] = cnt;
    }
    __syncthreads();
    const int cnt = s_misc[0];

    // Warp tiling: 4(m) x 2(n), warp = 32m x 64n
    const int wm32 = (wid & 3) * 32;
    const int wn64 = (wid >> 2) * 64;
    const int nblk0 = (wid >> 2) * 2;   // warp's first 32-N mask block (0 or 2)

    // ldmatrix per-lane addressing components
    const int a_row = ((lane >> 3) & 1) * 8 + (lane & 7);
    const int a_ks  = (lane >> 4) & 1;
    const int b_r   = lane & 7;
    const int b_ks  = (lane >> 3) & 1;
    const int b_ts  = (lane >> 4) & 1;

    // cp.async coords
    const int lrow = tid >> 3;        // 0..31 (+32*i)
    const int lc16 = tid & 7;         // 16B segment within 128B row

    float acc[2][8][4];
#pragma unroll
    for (int mt = 0; mt < 2; mt++)
#pragma unroll
        for (int nt = 0; nt < 8; nt++)
#pragma unroll
            for (int q = 0; q < 4; q++) acc[mt][nt][q] = 0.f;

#define LOAD_CHUNK(KB, BUF)                                                        \
    do {                                                                           \
        const int kb_ = (KB);                                                      \
        const uint32_t ab_ = smb + SM_A(BUF);                                      \
        const uint32_t wb_ = smb + SM_W(BUF);                                      \
        const __nv_bfloat16* ga_ = d_A2 + (size_t)m0 * twoK + (size_t)kb_ * 64;    \
        const __nv_bfloat16* gw_ = d_W2 + (size_t)n0 * twoK + (size_t)kb_ * 64;    \
        _Pragma("unroll")                                                          \
        for (int it_ = 0; it_ < 4; it_++) {                                        \
            const int row_ = lrow + it_ * 32;                                      \
            const uint32_t so_ = SWZ(row_ * 128 + lc16 * 16);                      \
            cp16(ab_ + so_, ga_ + (size_t)row_ * twoK + lc16 * 8, 16);             \
            const int sz_ = s_flags[((row_ >> 5) << 8) + kb_] ? 16 : 0;            \
            cp16(wb_ + so_, gw_ + (size_t)row_ * twoK + lc16 * 8, sz_);            \
        }                                                                          \
        cp_commit();                                                               \
    } while (0)

    if (cnt > 0) {
        LOAD_CHUNK((int)s_list[0], 0);
        if (cnt > 1) LOAD_CHUNK((int)s_list[1], 1);

        int cur = 0;
        for (int i = 0; i < cnt; i++) {
            if (i + 1 < cnt) cp_wait<1>(); else cp_wait<0>();   // chunk i landed
            __syncthreads();                                    // single barrier/chunk
            if (i + 2 < cnt) {
                int nxt = cur + 2; if (nxt >= 3) nxt -= 3;
                LOAD_CHUNK((int)s_list[i + 2], nxt);            // overlaps with compute
            }

            const int kb = (int)s_list[i];
            const int f0 = s_flags[nblk0 * 256 + kb];           // warp's N block 0
            const int f1 = s_flags[(nblk0 + 1) * 256 + kb];     // warp's N block 1

            if (f0 | f1) {                                      // warp-uniform
                const uint32_t ab = smb + SM_A(cur);
                const uint32_t wb = smb + SM_W(cur);
#pragma unroll
                for (int s = 0; s < 2; s++) {
                    uint32_t ahi[2][4], alo[2][4];
#pragma unroll
                    for (int mt = 0; mt < 2; mt++) {
                        const uint32_t abase = (wm32 + mt * 16 + a_row) * 128 + s * 32 + a_ks * 16;
                        ldmx4(ahi[mt], ab + SWZ(abase));
                        ldmx4(alo[mt], ab + SWZ(abase + 64));
                    }
#pragma unroll
                    for (int h = 0; h < 2; h++) {               // 32-N halves
                        if (!(h ? f1 : f0)) continue;           // skip inactive block
                        uint32_t whi[2][4], wlo[2][4];
#pragma unroll
                        for (int g = 0; g < 2; g++) {
                            const int j4 = 2 * h + g;
                            const uint32_t wbase = (wn64 + (2 * j4 + b_ts) * 8 + b_r) * 128
                                                   + s * 32 + b_ks * 16;
                            ldmx4(whi[g], wb + SWZ(wbase));
                            ldmx4(wlo[g], wb + SWZ(wbase + 64));
                        }
                        // pass 1: Ahi*Whi, pass 2: Ahi*Wlo, pass 3: Alo*Whi
#pragma unroll
                        for (int mt = 0; mt < 2; mt++)
#pragma unroll
                            for (int q = 0; q < 4; q++)
                                mma16816(acc[mt][4 * h + q], ahi[mt], &whi[q >> 1][(q & 1) * 2]);
#pragma unroll
                        for (int mt = 0; mt < 2; mt++)
#pragma unroll
                            for (int q = 0; q < 4; q++)
                                mma16816(acc[mt][4 * h + q], ahi[mt], &wlo[q >> 1][(q & 1) * 2]);
#pragma unroll
                        for (int mt = 0; mt < 2; mt++)
#pragma unroll
                            for (int q = 0; q < 4; q++)
                                mma16816(acc[mt][4 * h + q], alo[mt], &whi[q >> 1][(q & 1) * 2]);
                    }
                }
            }
            if (++cur >= 3) cur = 0;
        }
    }

    // Epilogue: acc + bias -> C (skipped blocks: acc==0, bias still added)
#pragma unroll
    for (int mt = 0; mt < 2; mt++) {
        const int gm = m0 + wm32 + mt * 16 + (lane >> 2);
#pragma unroll
        for (int nt = 0; nt < 8; nt++) {
            const int bn = wn64 + nt * 8 + (lane & 3) * 2;
            const float b0 = s_bias[bn], b1 = s_bias[bn + 1];
            float2 o0 = make_float2(acc[mt][nt][0] + b0, acc[mt][nt][1] + b1);
            float2 o1 = make_float2(acc[mt][nt][2] + b0, acc[mt][nt][3] + b1);
            *(float2*)(C + (size_t)gm * N + n0 + bn)       = o0;
            *(float2*)(C + (size_t)(gm + 8) * N + n0 + bn) = o1;
        }
    }
#undef LOAD_CHUNK
}

// ---------------------------------------------------------------------------
// Launch: inputs [data(B,S,K) f32, mask(N,K) i32, weight(N,K) f32, bias(N) f32]
// ---------------------------------------------------------------------------
extern "C" void kernel_launch(void* const* d_in, const int* in_sizes, int n_in,
                              void* d_out, int out_size) {
    const float* data   = (const float*)d_in[0];
    const int*   mask   = (const int*)d_in[1];
    const float* weight = (const float*)d_in[2];
    const float* bias   = (const float*)d_in[3];
    float* out = (float*)d_out;

    const int N = in_sizes[3];
    const int K = in_sizes[1] / N;
    const int M = in_sizes[0] / K;
    const int Kb = K / 32;
    const int Nb = N / 32;

    cudaFuncSetAttribute(mma_gemm, cudaFuncAttributeMaxDynamicSharedMemorySize, SMEM_TOTAL);

    blockmask_kernel<<<Nb * Kb, 256>>>(mask, K, Kb);
    pack_a_kernel<<<M, 256>>>(data, K);
    pack_w_kernel<<<N, 256>>>(weight, K);

    dim3 grid(N / 128, M / 128);
    mma_gemm<<<grid, 256, SMEM_TOTAL>>>(bias, out, M, N, K, Kb);
}

// round 12
// speedup vs baseline: 1.9425x; 1.0326x over previous
#include <cuda_runtime.h>
#include <cuda_bf16.h>
#include <cstdint>

// ---------------------------------------------------------------------------
// Static device scratch
// ---------------------------------------------------------------------------
#define MMAX 4096
#define KMAX 4096
__device__ unsigned char d_bm[256 * 256];
__device__ __nv_bfloat16 d_A2[(size_t)MMAX * 2 * KMAX];   // 64 MB: A hi/lo packed
__device__ __nv_bfloat16 d_W2[(size_t)MMAX * 2 * KMAX];   // 64 MB: W hi/lo packed

// ---------------------------------------------------------------------------
// PTX helpers (sm_80-level features only: cp.async, ldmatrix, mma.sync)
// ---------------------------------------------------------------------------
__device__ __forceinline__ uint32_t smem_addr(const void* p) {
    uint32_t a;
    asm("{ .reg .u64 t; cvta.to.shared.u64 t, %1; cvt.u32.u64 %0, t; }" : "=r"(a) : "l"(p));
    return a;
}
__device__ __forceinline__ void cp16(uint32_t dst, const void* src, int srcsz) {
    asm volatile("cp.async.cg.shared.global [%0], [%1], 16, %2;"
                 :: "r"(dst), "l"(src), "r"(srcsz) : "memory");
}
__device__ __forceinline__ void cp_commit() { asm volatile("cp.async.commit_group;" ::: "memory"); }
template <int N> __device__ __forceinline__ void cp_wait() {
    asm volatile("cp.async.wait_group %0;" :: "n"(N) : "memory");
}
__device__ __forceinline__ void ldmx4(uint32_t* r, uint32_t a) {
    asm volatile("ldmatrix.sync.aligned.m8n8.x4.shared.b16 {%0,%1,%2,%3}, [%4];"
                 : "=r"(r[0]), "=r"(r[1]), "=r"(r[2]), "=r"(r[3]) : "r"(a));
}
__device__ __forceinline__ void mma16816(float* c, const uint32_t* a, const uint32_t* b) {
    asm volatile(
        "mma.sync.aligned.m16n8k16.row.col.f32.bf16.bf16.f32 "
        "{%0,%1,%2,%3}, {%4,%5,%6,%7}, {%8,%9}, {%0,%1,%2,%3};"
        : "+f"(c[0]), "+f"(c[1]), "+f"(c[2]), "+f"(c[3])
        : "r"(a[0]), "r"(a[1]), "r"(a[2]), "r"(a[3]), "r"(b[0]), "r"(b[1]));
}

#define SWZ(o) ((o) ^ (((o) >> 3) & 0x70))

// Dynamic smem layout: 3-stage pipeline, 32KB/stage (A 16KB | W 16KB)
#define SM_A(b)   ((b) * 32768)
#define SM_W(b)   ((b) * 32768 + 16384)
#define SM_FLAGS  98304    // 4*256 bytes
#define SM_LIST   99328    // 256 * u16
#define SM_BIAS   99840    // 128 * f32
#define SM_MISC   100352   // [0]=count
#define SMEM_TOTAL 101376

// ---------------------------------------------------------------------------
// Kernel 1: pool element mask [N,K] into 32x32 block activity d_bm[Nb,Kb]
// ---------------------------------------------------------------------------
__global__ void blockmask_kernel(const int* __restrict__ mask, int K, int Kb) {
    int nb = blockIdx.x / Kb;
    int kb = blockIdx.x - nb * Kb;
    int r  = threadIdx.x >> 3;
    int c4 = threadIdx.x & 7;
    const int4* p = (const int4*)(mask + (size_t)(nb * 32 + r) * K + kb * 32 + c4 * 4);
    int4 v = *p;
    int any = __syncthreads_or(v.x | v.y | v.z | v.w);
    if (threadIdx.x == 0) d_bm[nb * Kb + kb] = any ? 1 : 0;
}

// ---------------------------------------------------------------------------
// Kernel 2: pack fp32 -> bf16 hi/lo, chunk-interleaved per 32-K-chunk:
//   out[m][c*64 + j]      = bf16(x)     (j = k&31, c = k>>5)
//   out[m][c*64 + 32 + j] = bf16(x - hi)
// Each packed row chunk = 128 bytes = one SW128 swizzle atom row.
// ---------------------------------------------------------------------------
__device__ __forceinline__ void pack_row(const float* __restrict__ src,
                                         __nv_bfloat16* __restrict__ dst, int K) {
    const int m = blockIdx.x;
    const float* row = src + (size_t)m * K;
    __nv_bfloat16* out = dst + (size_t)m * 2 * K;
    for (int p = threadIdx.x; p < (K >> 1); p += blockDim.x) {
        int k = p << 1;
        float2 v = *(const float2*)(row + k);
        __nv_bfloat16 h0 = __float2bfloat16(v.x);
        __nv_bfloat16 h1 = __float2bfloat16(v.y);
        __nv_bfloat162 hv; hv.x = h0; hv.y = h1;
        __nv_bfloat162 lv;
        lv.x = __float2bfloat16(v.x - __bfloat162float(h0));
        lv.y = __float2bfloat16(v.y - __bfloat162float(h1));
        int c = k >> 5, j = k & 31;
        *(__nv_bfloat162*)(out + (size_t)c * 64 + j)      = hv;
        *(__nv_bfloat162*)(out + (size_t)c * 64 + 32 + j) = lv;
    }
}
__global__ void pack_a_kernel(const float* __restrict__ src, int K) { pack_row(src, d_A2, K); }
__global__ void pack_w_kernel(const float* __restrict__ src, int K) { pack_row(src, d_W2, K); }

// ---------------------------------------------------------------------------
// Kernel 3: block-sparse bf16x3 GEMM via mma.sync (HMMA.16816.F32.BF16).
// C[M,N] = A*W^T + bias. CTA: 128x128.
// NEW warp layout: 8 warps partitioned along M ONLY (16 M-rows each); every
// warp spans all 128 N and skips inactive 32-N blocks. All warps have
// IDENTICAL per-chunk work (= #active blocks) -> zero barrier imbalance
// (was max over 2 n-groups ~ +55%).
// 3-stage cp.async pipeline, ONE barrier per chunk (proven skeleton).
// ---------------------------------------------------------------------------
__global__ __launch_bounds__(256)
void mma_gemm(const float* __restrict__ bias, float* __restrict__ C,
              int M, int N, int K, int Kb)
{
    extern __shared__ __align__(1024) char sm[];
    const int tid  = threadIdx.x;
    const int lane = tid & 31;
    const int wid  = tid >> 5;
    const int n0 = blockIdx.x * 128;
    const int m0 = blockIdx.y * 128;
    const int nb0 = n0 >> 5;
    const size_t twoK = (size_t)2 * K;

    unsigned char*  s_flags = (unsigned char*)(sm + SM_FLAGS);
    unsigned short* s_list  = (unsigned short*)(sm + SM_LIST);
    float*          s_bias  = (float*)(sm + SM_BIAS);
    volatile int*   s_misc  = (volatile int*)(sm + SM_MISC);
    const uint32_t smb = smem_addr(sm);

    for (int i = tid; i < 4 * Kb; i += 256) {
        int r = i / Kb, c = i - r * Kb;
        s_flags[r * 256 + c] = d_bm[(size_t)(nb0 + r) * Kb + c];
    }
    if (tid < 128) s_bias[tid] = bias[n0 + tid];
    __syncthreads();
    if (tid == 0) {
        int cnt = 0;
        for (int kb = 0; kb < Kb; kb++)
            if (s_flags[kb] | s_flags[256 + kb] | s_flags[512 + kb] | s_flags[768 + kb])
                s_list[cnt++] = (unsigned short)kb;
        s_misc[0] = cnt;
    }
    __syncthreads();
    const int cnt = s_misc[0];

    // Warp tiling: M-only partition; warp owns rows [wid*16, wid*16+16), all 128 N
    const int wm16 = wid * 16;

    // ldmatrix per-lane addressing components
    const int a_row = ((lane >> 3) & 1) * 8 + (lane & 7);
    const int a_ks  = (lane >> 4) & 1;
    const int b_r   = lane & 7;
    const int b_ks  = (lane >> 3) & 1;
    const int b_ts  = (lane >> 4) & 1;

    // cp.async coords
    const int lrow = tid >> 3;        // 0..31 (+32*i)
    const int lc16 = tid & 7;         // 16B segment within 128B row

    float acc[16][4];                 // 16 n8-tiles covering 128 N
#pragma unroll
    for (int nt = 0; nt < 16; nt++)
#pragma unroll
        for (int q = 0; q < 4; q++) acc[nt][q] = 0.f;

#define LOAD_CHUNK(KB, BUF)                                                        \
    do {                                                                           \
        const int kb_ = (KB);                                                      \
        const uint32_t ab_ = smb + SM_A(BUF);                                      \
        const uint32_t wb_ = smb + SM_W(BUF);                                      \
        const __nv_bfloat16* ga_ = d_A2 + (size_t)m0 * twoK + (size_t)kb_ * 64;    \
        const __nv_bfloat16* gw_ = d_W2 + (size_t)n0 * twoK + (size_t)kb_ * 64;    \
        _Pragma("unroll")                                                          \
        for (int it_ = 0; it_ < 4; it_++) {                                        \
            const int row_ = lrow + it_ * 32;                                      \
            const uint32_t so_ = SWZ(row_ * 128 + lc16 * 16);                      \
            cp16(ab_ + so_, ga_ + (size_t)row_ * twoK + lc16 * 8, 16);             \
            const int sz_ = s_flags[((row_ >> 5) << 8) + kb_] ? 16 : 0;            \
            cp16(wb_ + so_, gw_ + (size_t)row_ * twoK + lc16 * 8, sz_);            \
        }                                                                          \
        cp_commit();                                                               \
    } while (0)

    if (cnt > 0) {
        LOAD_CHUNK((int)s_list[0], 0);
        if (cnt > 1) LOAD_CHUNK((int)s_list[1], 1);

        int cur = 0;
        for (int i = 0; i < cnt; i++) {
            if (i + 1 < cnt) cp_wait<1>(); else cp_wait<0>();   // chunk i landed
            __syncthreads();                                    // single barrier/chunk
            if (i + 2 < cnt) {
                int nxt = cur + 2; if (nxt >= 3) nxt -= 3;
                LOAD_CHUNK((int)s_list[i + 2], nxt);            // overlaps with compute
            }

            const int kb = (int)s_list[i];
            const int f0 = s_flags[kb];
            const int f1 = s_flags[256 + kb];
            const int f2 = s_flags[512 + kb];
            const int f3 = s_flags[768 + kb];
            const int fl[4] = {f0, f1, f2, f3};

            const uint32_t ab = smb + SM_A(cur);
            const uint32_t wb = smb + SM_W(cur);
#pragma unroll
            for (int s = 0; s < 2; s++) {
                uint32_t ahi[4], alo[4];
                {
                    const uint32_t abase = (wm16 + a_row) * 128 + s * 32 + a_ks * 16;
                    ldmx4(ahi, ab + SWZ(abase));
                    ldmx4(alo, ab + SWZ(abase + 64));
                }
#pragma unroll
                for (int h = 0; h < 4; h++) {                  // 32-N blocks
                    if (!fl[h]) continue;                      // skip inactive
                    uint32_t whi[2][4], wlo[2][4];
#pragma unroll
                    for (int g = 0; g < 2; g++) {
                        const uint32_t wbase = (h * 32 + (2 * g + b_ts) * 8 + b_r) * 128
                                               + s * 32 + b_ks * 16;
                        ldmx4(whi[g], wb + SWZ(wbase));
                        ldmx4(wlo[g], wb + SWZ(wbase + 64));
                    }
                    // 3 passes x 4 n8-tiles
#pragma unroll
                    for (int q = 0; q < 4; q++)
                        mma16816(acc[4 * h + q], ahi, &whi[q >> 1][(q & 1) * 2]);
#pragma unroll
                    for (int q = 0; q < 4; q++)
                        mma16816(acc[4 * h + q], ahi, &wlo[q >> 1][(q & 1) * 2]);
#pragma unroll
                    for (int q = 0; q < 4; q++)
                        mma16816(acc[4 * h + q], alo, &whi[q >> 1][(q & 1) * 2]);
                }
            }
            if (++cur >= 3) cur = 0;
        }
    }

    // Epilogue: acc + bias -> C (skipped blocks: acc==0, bias still added)
    {
        const int gm = m0 + wm16 + (lane >> 2);
#pragma unroll
        for (int nt = 0; nt < 16; nt++) {
            const int bn = nt * 8 + (lane & 3) * 2;
            const float b0 = s_bias[bn], b1 = s_bias[bn + 1];
            float2 o0 = make_float2(acc[nt][0] + b0, acc[nt][1] + b1);
            float2 o1 = make_float2(acc[nt][2] + b0, acc[nt][3] + b1);
            *(float2*)(C + (size_t)gm * N + n0 + bn)       = o0;
            *(float2*)(C + (size_t)(gm + 8) * N + n0 + bn) = o1;
        }
    }
#undef LOAD_CHUNK
}

// ---------------------------------------------------------------------------
// Launch: inputs [data(B,S,K) f32, mask(N,K) i32, weight(N,K) f32, bias(N) f32]
// ---------------------------------------------------------------------------
extern "C" void kernel_launch(void* const* d_in, const int* in_sizes, int n_in,
                              void* d_out, int out_size) {
    const float* data   = (const float*)d_in[0];
    const int*   mask   = (const int*)d_in[1];
    const float* weight = (const float*)d_in[2];
    const float* bias   = (const float*)d_in[3];
    float* out = (float*)d_out;

    const int N = in_sizes[3];
    const int K = in_sizes[1] / N;
    const int M = in_sizes[0] / K;
    const int Kb = K / 32;
    const int Nb = N / 32;

    cudaFuncSetAttribute(mma_gemm, cudaFuncAttributeMaxDynamicSharedMemorySize, SMEM_TOTAL);

    blockmask_kernel<<<Nb * Kb, 256>>>(mask, K, Kb);
    pack_a_kernel<<<M, 256>>>(data, K);
    pack_w_kernel<<<N, 256>>>(weight, K);

    dim3 grid(N / 128, M / 128);
    mma_gemm<<<grid, 256, SMEM_TOTAL>>>(bias, out, M, N, K, Kb);
}